// round 5
// baseline (speedup 1.0000x reference)
#include <cuda_runtime.h>
#include <cuda_bf16.h>
#include <math.h>
#include <stdint.h>

// ---------------------------------------------------------------------------
// Problem constants
// ---------------------------------------------------------------------------
#define NTOK 8192           // 8 * 32 * 32 tokens at stride 32
#define C    768            // channels
#define NE   4              // experts

#define S4_ELEMS  50331648  // 8*96*256*256
#define S8_ELEMS  25165824  // 8*192*128*128
#define S16_ELEMS 12582912  // 8*384*64*64
#define OFF_S8   50331648
#define OFF_S16  75497472
#define OFF_S32  88080384

// GEMM tiling (tf32 mma path)
#define TBM 128
#define TBN 128
#define TBK 16
#define AS_STRIDE 20        // 16 + 4 floats  (conflict-free frag loads)
#define BS_STRIDE 136       // 128 + 8 floats (conflict-free frag loads)
#define AS_F (TBM * AS_STRIDE)           // 2560 floats / stage
#define BS_F (TBK * BS_STRIDE)           // 2176 floats / stage
#define AS_BYTES (AS_F * 4)              // 10240
#define BS_BYTES (BS_F * 4)              // 8704
#define STAGES 3
#define SMEM_DYN_BYTES (STAGES * (AS_BYTES + BS_BYTES))   // 56832

#define MT (NTOK / TBM)     // 64 m-tiles
#define NT (C / TBN)        // 6  n-tiles
#define NB_COPY 148         // copy blocks appended per GEMM launch

// ---------------------------------------------------------------------------
// Scratch (device globals: no allocation allowed)
// ---------------------------------------------------------------------------
__device__ float g_X [NTOK * C];   // tokens [N, C]; reused as Y (expert output) later
__device__ float g_G1[NTOK * C];   // gate hidden
__device__ float g_H [NTOK * C];   // expert hidden (compact, perm order)
__device__ int   g_top[NTOK];
__device__ float g_gv[NTOK];
__device__ int   g_perm[NTOK];     // compact pos -> token id
__device__ int   g_tok2g[NTOK];    // token id -> compact pos
__device__ int   g_counts[NE];
__device__ int   g_offsets[NE + 1];
__device__ int   g_fill[NE];

// ---------------------------------------------------------------------------
// Helpers
// ---------------------------------------------------------------------------
__device__ __forceinline__ float gelu_tanh(float x) {
    // jax.nn.gelu(approximate=True)
    float x3 = x * x * x;
    return 0.5f * x * (1.0f + tanhf(0.7978845608028654f * x + 0.035677408136300125f * x3));
}

__device__ __forceinline__ void cp_async16(uint32_t smem_dst, const float* gsrc, bool valid) {
    int sz = valid ? 16 : 0;
    asm volatile("cp.async.cg.shared.global [%0], [%1], 16, %2;\n"
                 :: "r"(smem_dst), "l"(gsrc), "r"(sz));
}
__device__ __forceinline__ void cp_commit() {
    asm volatile("cp.async.commit_group;\n");
}
__device__ __forceinline__ void cp_wait1() {
    asm volatile("cp.async.wait_group 1;\n");
}

__device__ __forceinline__ void mma_tf32(float* c, const uint32_t* a, const uint32_t* b) {
    asm volatile(
        "mma.sync.aligned.m16n8k8.row.col.f32.tf32.tf32.f32 "
        "{%0,%1,%2,%3},{%4,%5,%6,%7},{%8,%9},{%0,%1,%2,%3};\n"
        : "+f"(c[0]), "+f"(c[1]), "+f"(c[2]), "+f"(c[3])
        : "r"(a[0]), "r"(a[1]), "r"(a[2]), "r"(a[3]), "r"(b[0]), "r"(b[1]));
}

// split f into hi (top 10 mantissa bits, exact tf32) + lo (exact remainder)
__device__ __forceinline__ void split_tf32(float f, uint32_t& hi, uint32_t& lo) {
    uint32_t b = __float_as_uint(f);
    hi = b & 0xFFFFE000u;
    float l = f - __uint_as_float(hi);
    lo = __float_as_uint(l);
}

// ---------------------------------------------------------------------------
// 1. BCHW -> [N, C] transpose of s32 (+ counter reset in block 0)
// ---------------------------------------------------------------------------
__global__ void transpose_k(const float* __restrict__ s32) {
    __shared__ float tile[32][33];
    int b = blockIdx.z, c0 = blockIdx.y * 32, hw0 = blockIdx.x * 32;
    int tx = threadIdx.x, ty = threadIdx.y;   // (32, 8)
    if (blockIdx.x == 0 && blockIdx.y == 0 && blockIdx.z == 0 && ty == 0 && tx < NE)
        g_counts[tx] = 0;
    const float* src = s32 + (b * C + c0) * 1024 + hw0;
    #pragma unroll
    for (int j = 0; j < 32; j += 8)
        tile[ty + j][tx] = src[(ty + j) * 1024 + tx];
    __syncthreads();
    float* dst = g_X + (b * 1024 + hw0) * C + c0;
    #pragma unroll
    for (int j = 0; j < 32; j += 8)
        dst[(ty + j) * C + tx] = tile[tx][ty + j];
}

// ---------------------------------------------------------------------------
// tf32 tensor-core GEMM, 3-stage cp.async pipeline, with fused copy blocks.
//   MODE 0 (SPLIT=1): G1 = gelu(X @ gate_w1 + b1)               A=g_X,  Out=g_G1
//   MODE 1 (SPLIT=0): H  = gelu(gather(X,perm) @ ew1[e] + b1)   A=g_X,  Out=g_H
//   MODE 2 (SPLIT=0): Y  = (H @ ew2[e] + b2) * gate_val         A=g_H,  Out=g_X
// Flat grid: blocks [0, nbGemm) do GEMM, [nbGemm, nbGemm+NB_COPY) do a
// grid-stride float4 passthrough copy (overlaps DRAM copy with tensor math).
// Block 128x128, 8 warps (2m x 4n), warp tile 64x32, mma m16n8k8.
// ---------------------------------------------------------------------------
template <int MODE, int SPLIT>
__launch_bounds__(256)
__global__ void mma_gemm_k(const float* __restrict__ Wall,
                           const float* __restrict__ Ball,
                           const float4* __restrict__ csrc,
                           float4* __restrict__ cdst,
                           int cnt4, int nbGemm) {
    const int blk = blockIdx.x;
    const int tid = threadIdx.x;

    // ---- copy role -------------------------------------------------------
    if (blk >= nbGemm) {
        size_t i = (size_t)(blk - nbGemm) * 256 + tid;
        const size_t stride = (size_t)NB_COPY * 256;
        for (; i < (size_t)cnt4; i += stride)
            cdst[i] = csrc[i];
        return;
    }

    // ---- GEMM role -------------------------------------------------------
    int e, bx, by;
    if (MODE == 0) { e = 0; bx = blk & (MT - 1); by = blk >> 6; }
    else { e = blk / (MT * NT); int r = blk - e * (MT * NT); bx = r & (MT - 1); by = r >> 6; }

    int base, cnt;
    if (MODE == 0) { base = 0; cnt = NTOK; }
    else           { base = g_offsets[e]; cnt = g_offsets[e + 1] - base; }

    const int m0 = bx * TBM;
    if (m0 >= cnt) return;
    const int n0 = by * TBN;

    const float* A    = (MODE == 2) ? g_H : g_X;
    float*       Out  = (MODE == 0) ? g_G1 : ((MODE == 1) ? g_H : g_X);
    const float* W    = Wall + ((MODE == 0) ? 0 : (size_t)e * C * C);
    const float* bias = Ball + ((MODE == 0) ? 0 : e * C);

    extern __shared__ float smem_dyn[];
    float* AsBase = smem_dyn;                     // [STAGES][AS_F]
    float* BsBase = smem_dyn + STAGES * AS_F;     // [STAGES][BS_F]
    const uint32_t sA = (uint32_t)__cvta_generic_to_shared(AsBase);
    const uint32_t sB = (uint32_t)__cvta_generic_to_shared(BsBase);

    const int wid  = tid >> 5;
    const int lane = tid & 31;
    const int g    = lane >> 2;     // groupID 0..7
    const int tig  = lane & 3;      // threadID in group
    const int mW   = (wid & 1) * 64;
    const int nW   = (wid >> 1) * 32;

    // ---- loader setup: 2 x 16B A chunks + 2 x 16B B chunks per thread/stage
    const float* srcA[2]; uint32_t dstA[2]; bool vA[2];
    #pragma unroll
    for (int i = 0; i < 2; i++) {
        int q   = tid + i * 256;
        int kq  = q >> 7;           // 0..3
        int row = q & 127;          // 0..127
        int m   = m0 + row;
        bool v  = (m < cnt);
        int ar  = 0;
        if (v) {
            if      (MODE == 1) ar = g_perm[base + m];
            else if (MODE == 2) ar = base + m;
            else                ar = m;
        }
        srcA[i] = A + (size_t)ar * C + kq * 4;
        dstA[i] = (uint32_t)(row * AS_STRIDE + kq * 4) * 4u;
        vA[i]   = v;
    }
    const float* srcB[2]; uint32_t dstB[2];
    #pragma unroll
    for (int i = 0; i < 2; i++) {
        int q  = tid + i * 256;
        int k  = q >> 5;            // 0..15
        int n4 = (q & 31) * 4;      // 0..124
        srcB[i] = W + (size_t)k * C + n0 + n4;
        dstB[i] = (uint32_t)(k * BS_STRIDE + n4) * 4u;
    }

    float acc[4][4][4];
    #pragma unroll
    for (int mt = 0; mt < 4; mt++)
        #pragma unroll
        for (int nt = 0; nt < 4; nt++)
            #pragma unroll
            for (int r = 0; r < 4; r++) acc[mt][nt][r] = 0.f;

    const int T = C / TBK;  // 48 stages

    // prologue: stages 0 and 1
    #pragma unroll
    for (int s = 0; s < 2; s++) {
        const int kf = s * TBK;
        #pragma unroll
        for (int i = 0; i < 2; i++)
            cp_async16(sA + s * AS_BYTES + dstA[i], srcA[i] + kf, vA[i]);
        #pragma unroll
        for (int i = 0; i < 2; i++)
            cp_async16(sB + s * BS_BYTES + dstB[i], srcB[i] + (size_t)kf * C, true);
        cp_commit();
    }

    int cur = 0;
    for (int t = 0; t < T; t++) {
        cp_wait1();            // stage t resident (<=1 group pending)
        __syncthreads();

        if (t + 2 < T) {
            int nxt = cur + 2; if (nxt >= STAGES) nxt -= STAGES;
            const int kf = (t + 2) * TBK;
            #pragma unroll
            for (int i = 0; i < 2; i++)
                cp_async16(sA + nxt * AS_BYTES + dstA[i], srcA[i] + kf, vA[i]);
            #pragma unroll
            for (int i = 0; i < 2; i++)
                cp_async16(sB + nxt * BS_BYTES + dstB[i], srcB[i] + (size_t)kf * C, true);
        }
        cp_commit();           // commit every iter (keeps group accounting uniform)

        const float* Asb = AsBase + cur * AS_F;
        const float* Bsb = BsBase + cur * BS_F;

        #pragma unroll
        for (int ks = 0; ks < 2; ks++) {
            const int kk = ks * 8;
            uint32_t bh[4][2], bl[4][2];
            #pragma unroll
            for (int nt = 0; nt < 4; nt++) {
                float f0 = Bsb[(kk + tig)     * BS_STRIDE + nW + nt * 8 + g];
                float f1 = Bsb[(kk + tig + 4) * BS_STRIDE + nW + nt * 8 + g];
                if (SPLIT) {
                    split_tf32(f0, bh[nt][0], bl[nt][0]);
                    split_tf32(f1, bh[nt][1], bl[nt][1]);
                } else {
                    bh[nt][0] = __float_as_uint(f0);
                    bh[nt][1] = __float_as_uint(f1);
                }
            }
            #pragma unroll
            for (int mt = 0; mt < 4; mt++) {
                const int r0 = mW + mt * 16 + g;
                float f0 = Asb[ r0      * AS_STRIDE + kk + tig];
                float f1 = Asb[(r0 + 8) * AS_STRIDE + kk + tig];
                float f2 = Asb[ r0      * AS_STRIDE + kk + tig + 4];
                float f3 = Asb[(r0 + 8) * AS_STRIDE + kk + tig + 4];
                uint32_t ah[4], al[4];
                if (SPLIT) {
                    split_tf32(f0, ah[0], al[0]);
                    split_tf32(f1, ah[1], al[1]);
                    split_tf32(f2, ah[2], al[2]);
                    split_tf32(f3, ah[3], al[3]);
                } else {
                    ah[0] = __float_as_uint(f0);
                    ah[1] = __float_as_uint(f1);
                    ah[2] = __float_as_uint(f2);
                    ah[3] = __float_as_uint(f3);
                }
                #pragma unroll
                for (int nt = 0; nt < 4; nt++) {
                    mma_tf32(acc[mt][nt], ah, bh[nt]);
                    if (SPLIT) {
                        mma_tf32(acc[mt][nt], al, bh[nt]);
                        mma_tf32(acc[mt][nt], ah, bl[nt]);
                    }
                }
            }
        }
        __syncthreads();
        cur++; if (cur >= STAGES) cur -= STAGES;
    }

    // ---- epilogue
    #pragma unroll
    for (int mt = 0; mt < 4; mt++) {
        #pragma unroll
        for (int half = 0; half < 2; half++) {
            const int m = m0 + mW + mt * 16 + g + half * 8;
            if (m >= cnt) continue;
            int drow; float gv = 1.f;
            if (MODE == 0) drow = m;
            else           drow = base + m;
            if (MODE == 2) gv = g_gv[g_perm[base + m]];
            float* orow = Out + (size_t)drow * C;
            #pragma unroll
            for (int nt = 0; nt < 4; nt++) {
                const int col = n0 + nW + nt * 8 + tig * 2;
                float2 bv = *(const float2*)(bias + col);
                float v0 = acc[mt][nt][half * 2 + 0] + bv.x;
                float v1 = acc[mt][nt][half * 2 + 1] + bv.y;
                if (MODE == 2) { v0 *= gv; v1 *= gv; }
                else           { v0 = gelu_tanh(v0); v1 = gelu_tanh(v1); }
                *(float2*)(orow + col) = make_float2(v0, v1);
            }
        }
    }
}

// ---------------------------------------------------------------------------
// 3. logits = G1 @ gate_w2 + b2 -> softmax -> top-1 idx + gate value
// ---------------------------------------------------------------------------
__global__ void gate_k(const float* __restrict__ w2, const float* __restrict__ b2) {
    int warp = (blockIdx.x * blockDim.x + threadIdx.x) >> 5;
    int lane = threadIdx.x & 31;
    if (warp >= NTOK) return;
    const float* g = g_G1 + (size_t)warp * C;
    float l0 = 0.f, l1 = 0.f, l2 = 0.f, l3 = 0.f;
    for (int c = lane; c < C; c += 32) {
        float x = g[c];
        float4 wv = *(const float4*)(w2 + c * 4);
        l0 = fmaf(x, wv.x, l0);
        l1 = fmaf(x, wv.y, l1);
        l2 = fmaf(x, wv.z, l2);
        l3 = fmaf(x, wv.w, l3);
    }
    #pragma unroll
    for (int o = 16; o; o >>= 1) {
        l0 += __shfl_xor_sync(0xffffffffu, l0, o);
        l1 += __shfl_xor_sync(0xffffffffu, l1, o);
        l2 += __shfl_xor_sync(0xffffffffu, l2, o);
        l3 += __shfl_xor_sync(0xffffffffu, l3, o);
    }
    if (lane == 0) {
        l0 += b2[0]; l1 += b2[1]; l2 += b2[2]; l3 += b2[3];
        float m = l0; int idx = 0;
        if (l1 > m) { m = l1; idx = 1; }   // strict '>' keeps first max (jnp.argmax)
        if (l2 > m) { m = l2; idx = 2; }
        if (l3 > m) { m = l3; idx = 3; }
        float s = expf(l0 - m) + expf(l1 - m) + expf(l2 - m) + expf(l3 - m);
        g_top[warp] = idx;
        g_gv[warp]  = 1.0f / s;            // exp(l_top - m) == 1
        atomicAdd(&g_counts[idx], 1);
    }
}

// ---------------------------------------------------------------------------
// 4. tiny exclusive scan + reset fill cursors
// ---------------------------------------------------------------------------
__global__ void scan_k() {
    if (threadIdx.x == 0) {
        int s = 0;
        #pragma unroll
        for (int e = 0; e < NE; e++) {
            g_offsets[e] = s;
            s += g_counts[e];
            g_fill[e] = 0;
        }
        g_offsets[NE] = s;
    }
}

// ---------------------------------------------------------------------------
// 5. build permutation (token -> compact position, grouped by expert)
// ---------------------------------------------------------------------------
__global__ void perm_k() {
    int n = blockIdx.x * blockDim.x + threadIdx.x;
    if (n >= NTOK) return;
    int e = g_top[n];
    int pos = atomicAdd(&g_fill[e], 1);
    int gg = g_offsets[e] + pos;
    g_perm[gg]  = n;
    g_tok2g[n]  = gg;
}

// ---------------------------------------------------------------------------
// 8. coalesced scatter back to BCHW + residual
// ---------------------------------------------------------------------------
__global__ void scatter_k(const float* __restrict__ s32, float* __restrict__ out32) {
    __shared__ float tile[32][33];
    int b = blockIdx.z, c0 = blockIdx.y * 32, hw0 = blockIdx.x * 32;
    int tx = threadIdx.x, ty = threadIdx.y;   // (32, 8)
    for (int t = ty; t < 32; t += 8) {
        int n = b * 1024 + hw0 + t;
        int gg = g_tok2g[n];
        tile[t][tx] = g_X[(size_t)gg * C + c0 + tx];
    }
    __syncthreads();
    int ibase = b * (C * 1024) + hw0;
    #pragma unroll
    for (int j = 0; j < 4; j++) {
        int c = c0 + ty + 8 * j;
        int idx = ibase + c * 1024 + tx;
        out32[idx] = tile[tx][ty + 8 * j] + s32[idx];
    }
}

// ---------------------------------------------------------------------------
// launch
// ---------------------------------------------------------------------------
extern "C" void kernel_launch(void* const* d_in, const int* in_sizes, int n_in,
                              void* d_out, int out_size) {
    const float* s4  = (const float*)d_in[0];
    const float* s8  = (const float*)d_in[1];
    const float* s16 = (const float*)d_in[2];
    const float* s32 = (const float*)d_in[3];
    const float* gw1 = (const float*)d_in[4];
    const float* gb1 = (const float*)d_in[5];
    const float* gw2 = (const float*)d_in[6];
    const float* gb2 = (const float*)d_in[7];
    const float* ew1 = (const float*)d_in[8];
    const float* eb1 = (const float*)d_in[9];
    const float* ew2 = (const float*)d_in[10];
    const float* eb2 = (const float*)d_in[11];
    float* out = (float*)d_out;

    // opt-in dynamic smem (> 48KB) for each GEMM instantiation (idempotent)
    cudaFuncSetAttribute(mma_gemm_k<0, 1>, cudaFuncAttributeMaxDynamicSharedMemorySize, SMEM_DYN_BYTES);
    cudaFuncSetAttribute(mma_gemm_k<1, 0>, cudaFuncAttributeMaxDynamicSharedMemorySize, SMEM_DYN_BYTES);
    cudaFuncSetAttribute(mma_gemm_k<2, 0>, cudaFuncAttributeMaxDynamicSharedMemorySize, SMEM_DYN_BYTES);

    transpose_k<<<dim3(32, 24, 8), dim3(32, 8)>>>(s32);

    // gate hidden: G1 = gelu(X @ gw1 + gb1)   (split-tf32) + s4 copy fused
    mma_gemm_k<0, 1><<<MT * NT + NB_COPY, 256, SMEM_DYN_BYTES>>>(
        gw1, gb1, (const float4*)s4, (float4*)out, S4_ELEMS / 4, MT * NT);

    // routing
    gate_k<<<(NTOK * 32) / 256, 256>>>(gw2, gb2);
    scan_k<<<1, 1>>>();
    perm_k<<<NTOK / 256, 256>>>();

    // expert up:   H = gelu(gather(X) @ ew1[e] + eb1[e])   (tf32) + s8 copy fused
    mma_gemm_k<1, 0><<<MT * NT * NE + NB_COPY, 256, SMEM_DYN_BYTES>>>(
        ew1, eb1, (const float4*)s8, (float4*)(out + OFF_S8), S8_ELEMS / 4, MT * NT * NE);

    // expert down: Y = (H @ ew2[e] + eb2[e]) * gate_val    (tf32) + s16 copy fused
    mma_gemm_k<2, 0><<<MT * NT * NE + NB_COPY, 256, SMEM_DYN_BYTES>>>(
        ew2, eb2, (const float4*)s16, (float4*)(out + OFF_S16), S16_ELEMS / 4, MT * NT * NE);

    // scatter + residual into out32
    scatter_k<<<dim3(32, 24, 8), dim3(32, 8)>>>(s32, out + OFF_S32);
}

// round 6
// speedup vs baseline: 1.3818x; 1.3818x over previous
#include <cuda_runtime.h>
#include <cuda_bf16.h>
#include <math.h>
#include <stdint.h>

// ---------------------------------------------------------------------------
// Problem constants
// ---------------------------------------------------------------------------
#define NTOK 8192           // 8 * 32 * 32 tokens at stride 32
#define C    768            // channels
#define NE   4              // experts

#define S4_ELEMS  50331648  // 8*96*256*256
#define S8_ELEMS  25165824  // 8*192*128*128
#define S16_ELEMS 12582912  // 8*384*64*64
#define OFF_S8   50331648
#define OFF_S16  75497472
#define OFF_S32  88080384

// GEMM tiling (tf32 mma path) — identical to the 565us R3 kernel
#define TBM 128
#define TBN 128
#define TBK 16
#define AS_STRIDE 20        // 16 + 4 floats  (conflict-free frag loads)
#define BS_STRIDE 136       // 128 + 8 floats (conflict-free frag loads)
#define AS_BYTES (TBM * AS_STRIDE * 4)   // 10240
#define BS_BYTES (TBK * BS_STRIDE * 4)   // 8704

#define MT (NTOK / TBM)     // 64 m-tiles
#define NT (C / TBN)        // 6  n-tiles
#define NB_COPY 148         // copy blocks PREPENDED per GEMM launch (1 per SM in wave 1)

// ---------------------------------------------------------------------------
// Scratch (device globals: no allocation allowed)
// ---------------------------------------------------------------------------
__device__ float g_X [NTOK * C];   // tokens [N, C]; reused as Y (expert output) later
__device__ float g_G1[NTOK * C];   // gate hidden
__device__ float g_H [NTOK * C];   // expert hidden (compact, perm order)
__device__ int   g_top[NTOK];
__device__ float g_gv[NTOK];
__device__ int   g_perm[NTOK];     // compact pos -> token id
__device__ int   g_tok2g[NTOK];    // token id -> compact pos
__device__ int   g_counts[NE];
__device__ int   g_offsets[NE + 1];
__device__ int   g_fill[NE];

// ---------------------------------------------------------------------------
// Helpers
// ---------------------------------------------------------------------------
__device__ __forceinline__ float gelu_tanh(float x) {
    // jax.nn.gelu(approximate=True)
    float x3 = x * x * x;
    return 0.5f * x * (1.0f + tanhf(0.7978845608028654f * x + 0.035677408136300125f * x3));
}

__device__ __forceinline__ void cp_async16(uint32_t smem_dst, const float* gsrc, bool valid) {
    int sz = valid ? 16 : 0;
    asm volatile("cp.async.cg.shared.global [%0], [%1], 16, %2;\n"
                 :: "r"(smem_dst), "l"(gsrc), "r"(sz));
}
__device__ __forceinline__ void cp_commit() {
    asm volatile("cp.async.commit_group;\n");
}
__device__ __forceinline__ void cp_wait0() {
    asm volatile("cp.async.wait_group 0;\n");
}

__device__ __forceinline__ void mma_tf32(float* c, const uint32_t* a, const uint32_t* b) {
    asm volatile(
        "mma.sync.aligned.m16n8k8.row.col.f32.tf32.tf32.f32 "
        "{%0,%1,%2,%3},{%4,%5,%6,%7},{%8,%9},{%0,%1,%2,%3};\n"
        : "+f"(c[0]), "+f"(c[1]), "+f"(c[2]), "+f"(c[3])
        : "r"(a[0]), "r"(a[1]), "r"(a[2]), "r"(a[3]), "r"(b[0]), "r"(b[1]));
}

// split f into hi (top 10 mantissa bits, exact tf32) + lo (exact remainder)
__device__ __forceinline__ void split_tf32(float f, uint32_t& hi, uint32_t& lo) {
    uint32_t b = __float_as_uint(f);
    hi = b & 0xFFFFE000u;
    float l = f - __uint_as_float(hi);
    lo = __float_as_uint(l);
}

// ---------------------------------------------------------------------------
// 1. BCHW -> [N, C] transpose of s32 (+ counter reset in block 0)
// ---------------------------------------------------------------------------
__global__ void transpose_k(const float* __restrict__ s32) {
    __shared__ float tile[32][33];
    int b = blockIdx.z, c0 = blockIdx.y * 32, hw0 = blockIdx.x * 32;
    int tx = threadIdx.x, ty = threadIdx.y;   // (32, 8)
    if (blockIdx.x == 0 && blockIdx.y == 0 && blockIdx.z == 0 && ty == 0 && tx < NE)
        g_counts[tx] = 0;
    const float* src = s32 + (b * C + c0) * 1024 + hw0;
    #pragma unroll
    for (int j = 0; j < 32; j += 8)
        tile[ty + j][tx] = src[(ty + j) * 1024 + tx];
    __syncthreads();
    float* dst = g_X + (b * 1024 + hw0) * C + c0;
    #pragma unroll
    for (int j = 0; j < 32; j += 8)
        dst[(ty + j) * C + tx] = tile[tx][ty + j];
}

// ---------------------------------------------------------------------------
// tf32 tensor-core GEMM (R3's double-buffered cp.async pipeline) with copy
// blocks PREPENDED: blocks [0, NB_COPY) run a high-MLP grid-stride float4
// passthrough copy concurrently with the GEMM blocks (overlap DRAM with
// tensor math). Blocks [NB_COPY, NB_COPY + nbGemm) do the GEMM.
//   MODE 0 (SPLIT=1): G1 = gelu(X @ gate_w1 + b1)               A=g_X,  Out=g_G1
//   MODE 1 (SPLIT=0): H  = gelu(gather(X,perm) @ ew1[e] + b1)   A=g_X,  Out=g_H
//   MODE 2 (SPLIT=0): Y  = (H @ ew2[e] + b2) * gate_val         A=g_H,  Out=g_X
// Block 128x128, 8 warps (2m x 4n), warp tile 64x32, mma m16n8k8.
// ---------------------------------------------------------------------------
template <int MODE, int SPLIT>
__launch_bounds__(256)
__global__ void mma_gemm_k(const float* __restrict__ Wall,
                           const float* __restrict__ Ball,
                           const float4* __restrict__ csrc,
                           float4* __restrict__ cdst,
                           int cnt4) {
    const int blk = blockIdx.x;
    const int tid = threadIdx.x;

    // ---- copy role (wave-1 resident, 64B per thread per iter => ~2.4MB MLP)
    if (blk < NB_COPY) {
        // cnt4 is always a multiple of 1024, so each 1024-float4 window is full.
        size_t i = (size_t)blk * 1024 + tid;
        const size_t stride = (size_t)NB_COPY * 1024;
        for (; i < (size_t)cnt4; i += stride) {
            float4 a = csrc[i];
            float4 b = csrc[i + 256];
            float4 c = csrc[i + 512];
            float4 d = csrc[i + 768];
            cdst[i]       = a;
            cdst[i + 256] = b;
            cdst[i + 512] = c;
            cdst[i + 768] = d;
        }
        return;
    }

    // ---- GEMM role -------------------------------------------------------
    const int gblk = blk - NB_COPY;
    int e, bx, by;
    if (MODE == 0) { e = 0; bx = gblk & (MT - 1); by = gblk >> 6; }
    else { e = gblk / (MT * NT); int r = gblk - e * (MT * NT); bx = r & (MT - 1); by = r >> 6; }

    int base, cnt;
    if (MODE == 0) { base = 0; cnt = NTOK; }
    else           { base = g_offsets[e]; cnt = g_offsets[e + 1] - base; }

    const int m0 = bx * TBM;
    if (m0 >= cnt) return;
    const int n0 = by * TBN;

    const float* A    = (MODE == 2) ? g_H : g_X;
    float*       Out  = (MODE == 0) ? g_G1 : ((MODE == 1) ? g_H : g_X);
    const float* W    = Wall + ((MODE == 0) ? 0 : (size_t)e * C * C);
    const float* bias = Ball + ((MODE == 0) ? 0 : e * C);

    __shared__ __align__(16) float As[2][TBM * AS_STRIDE];  // [m][k]
    __shared__ __align__(16) float Bs[2][TBK * BS_STRIDE];  // [k][n]
    const uint32_t sA = (uint32_t)__cvta_generic_to_shared(&As[0][0]);
    const uint32_t sB = (uint32_t)__cvta_generic_to_shared(&Bs[0][0]);

    const int wid  = tid >> 5;
    const int lane = tid & 31;
    const int g    = lane >> 2;     // groupID 0..7
    const int tig  = lane & 3;      // threadID in group
    const int mW   = (wid & 1) * 64;
    const int nW   = (wid >> 1) * 32;

    // ---- loader setup: 2 x 16B A chunks + 2 x 16B B chunks per thread/stage
    const float* srcA[2]; uint32_t dstA[2]; bool vA[2];
    #pragma unroll
    for (int i = 0; i < 2; i++) {
        int q   = tid + i * 256;
        int kq  = q >> 7;           // 0..3
        int row = q & 127;          // 0..127
        int m   = m0 + row;
        bool v  = (m < cnt);
        int ar  = 0;
        if (v) {
            if      (MODE == 1) ar = g_perm[base + m];
            else if (MODE == 2) ar = base + m;
            else                ar = m;
        }
        srcA[i] = A + (size_t)ar * C + kq * 4;
        dstA[i] = (uint32_t)(row * AS_STRIDE + kq * 4) * 4u;
        vA[i]   = v;
    }
    const float* srcB[2]; uint32_t dstB[2];
    #pragma unroll
    for (int i = 0; i < 2; i++) {
        int q  = tid + i * 256;
        int k  = q >> 5;            // 0..15
        int n4 = (q & 31) * 4;      // 0..124
        srcB[i] = W + (size_t)k * C + n0 + n4;
        dstB[i] = (uint32_t)(k * BS_STRIDE + n4) * 4u;
    }

    float acc[4][4][4];
    #pragma unroll
    for (int mt = 0; mt < 4; mt++)
        #pragma unroll
        for (int nt = 0; nt < 4; nt++)
            #pragma unroll
            for (int r = 0; r < 4; r++) acc[mt][nt][r] = 0.f;

    const int T = C / TBK;  // 48 stages

    // prologue: stage 0
    #pragma unroll
    for (int i = 0; i < 2; i++) cp_async16(sA + dstA[i], srcA[i], vA[i]);
    #pragma unroll
    for (int i = 0; i < 2; i++) cp_async16(sB + dstB[i], srcB[i], true);
    cp_commit();

    for (int t = 0; t < T; t++) {
        const int cur = t & 1;
        cp_wait0();
        __syncthreads();

        if (t + 1 < T) {
            const int nxt = cur ^ 1;
            const int kf  = (t + 1) * TBK;
            #pragma unroll
            for (int i = 0; i < 2; i++)
                cp_async16(sA + nxt * AS_BYTES + dstA[i], srcA[i] + kf, vA[i]);
            #pragma unroll
            for (int i = 0; i < 2; i++)
                cp_async16(sB + nxt * BS_BYTES + dstB[i], srcB[i] + (size_t)kf * C, true);
            cp_commit();
        }

        const float* Asb = &As[cur][0];
        const float* Bsb = &Bs[cur][0];

        #pragma unroll
        for (int ks = 0; ks < 2; ks++) {
            const int kk = ks * 8;
            uint32_t bh[4][2], bl[4][2];
            #pragma unroll
            for (int nt = 0; nt < 4; nt++) {
                float f0 = Bsb[(kk + tig)     * BS_STRIDE + nW + nt * 8 + g];
                float f1 = Bsb[(kk + tig + 4) * BS_STRIDE + nW + nt * 8 + g];
                if (SPLIT) {
                    split_tf32(f0, bh[nt][0], bl[nt][0]);
                    split_tf32(f1, bh[nt][1], bl[nt][1]);
                } else {
                    bh[nt][0] = __float_as_uint(f0);
                    bh[nt][1] = __float_as_uint(f1);
                }
            }
            #pragma unroll
            for (int mt = 0; mt < 4; mt++) {
                const int r0 = mW + mt * 16 + g;
                float f0 = Asb[ r0      * AS_STRIDE + kk + tig];
                float f1 = Asb[(r0 + 8) * AS_STRIDE + kk + tig];
                float f2 = Asb[ r0      * AS_STRIDE + kk + tig + 4];
                float f3 = Asb[(r0 + 8) * AS_STRIDE + kk + tig + 4];
                uint32_t ah[4], al[4];
                if (SPLIT) {
                    split_tf32(f0, ah[0], al[0]);
                    split_tf32(f1, ah[1], al[1]);
                    split_tf32(f2, ah[2], al[2]);
                    split_tf32(f3, ah[3], al[3]);
                } else {
                    ah[0] = __float_as_uint(f0);
                    ah[1] = __float_as_uint(f1);
                    ah[2] = __float_as_uint(f2);
                    ah[3] = __float_as_uint(f3);
                }
                #pragma unroll
                for (int nt = 0; nt < 4; nt++) {
                    mma_tf32(acc[mt][nt], ah, bh[nt]);
                    if (SPLIT) {
                        mma_tf32(acc[mt][nt], al, bh[nt]);
                        mma_tf32(acc[mt][nt], ah, bl[nt]);
                    }
                }
            }
        }
        __syncthreads();
    }

    // ---- epilogue
    #pragma unroll
    for (int mt = 0; mt < 4; mt++) {
        #pragma unroll
        for (int half = 0; half < 2; half++) {
            const int m = m0 + mW + mt * 16 + g + half * 8;
            if (m >= cnt) continue;
            int drow; float gv = 1.f;
            if (MODE == 0) drow = m;
            else           drow = base + m;
            if (MODE == 2) gv = g_gv[g_perm[base + m]];
            float* orow = Out + (size_t)drow * C;
            #pragma unroll
            for (int nt = 0; nt < 4; nt++) {
                const int col = n0 + nW + nt * 8 + tig * 2;
                float2 bv = *(const float2*)(bias + col);
                float v0 = acc[mt][nt][half * 2 + 0] + bv.x;
                float v1 = acc[mt][nt][half * 2 + 1] + bv.y;
                if (MODE == 2) { v0 *= gv; v1 *= gv; }
                else           { v0 = gelu_tanh(v0); v1 = gelu_tanh(v1); }
                *(float2*)(orow + col) = make_float2(v0, v1);
            }
        }
    }
}

// ---------------------------------------------------------------------------
// 3. logits = G1 @ gate_w2 + b2 -> softmax -> top-1 idx + gate value
// ---------------------------------------------------------------------------
__global__ void gate_k(const float* __restrict__ w2, const float* __restrict__ b2) {
    int warp = (blockIdx.x * blockDim.x + threadIdx.x) >> 5;
    int lane = threadIdx.x & 31;
    if (warp >= NTOK) return;
    const float* g = g_G1 + (size_t)warp * C;
    float l0 = 0.f, l1 = 0.f, l2 = 0.f, l3 = 0.f;
    for (int c = lane; c < C; c += 32) {
        float x = g[c];
        float4 wv = *(const float4*)(w2 + c * 4);
        l0 = fmaf(x, wv.x, l0);
        l1 = fmaf(x, wv.y, l1);
        l2 = fmaf(x, wv.z, l2);
        l3 = fmaf(x, wv.w, l3);
    }
    #pragma unroll
    for (int o = 16; o; o >>= 1) {
        l0 += __shfl_xor_sync(0xffffffffu, l0, o);
        l1 += __shfl_xor_sync(0xffffffffu, l1, o);
        l2 += __shfl_xor_sync(0xffffffffu, l2, o);
        l3 += __shfl_xor_sync(0xffffffffu, l3, o);
    }
    if (lane == 0) {
        l0 += b2[0]; l1 += b2[1]; l2 += b2[2]; l3 += b2[3];
        float m = l0; int idx = 0;
        if (l1 > m) { m = l1; idx = 1; }   // strict '>' keeps first max (jnp.argmax)
        if (l2 > m) { m = l2; idx = 2; }
        if (l3 > m) { m = l3; idx = 3; }
        float s = expf(l0 - m) + expf(l1 - m) + expf(l2 - m) + expf(l3 - m);
        g_top[warp] = idx;
        g_gv[warp]  = 1.0f / s;            // exp(l_top - m) == 1
        atomicAdd(&g_counts[idx], 1);
    }
}

// ---------------------------------------------------------------------------
// 4. tiny exclusive scan + reset fill cursors
// ---------------------------------------------------------------------------
__global__ void scan_k() {
    if (threadIdx.x == 0) {
        int s = 0;
        #pragma unroll
        for (int e = 0; e < NE; e++) {
            g_offsets[e] = s;
            s += g_counts[e];
            g_fill[e] = 0;
        }
        g_offsets[NE] = s;
    }
}

// ---------------------------------------------------------------------------
// 5. build permutation (token -> compact position, grouped by expert)
// ---------------------------------------------------------------------------
__global__ void perm_k() {
    int n = blockIdx.x * blockDim.x + threadIdx.x;
    if (n >= NTOK) return;
    int e = g_top[n];
    int pos = atomicAdd(&g_fill[e], 1);
    int gg = g_offsets[e] + pos;
    g_perm[gg]  = n;
    g_tok2g[n]  = gg;
}

// ---------------------------------------------------------------------------
// 8. coalesced scatter back to BCHW + residual
// ---------------------------------------------------------------------------
__global__ void scatter_k(const float* __restrict__ s32, float* __restrict__ out32) {
    __shared__ float tile[32][33];
    int b = blockIdx.z, c0 = blockIdx.y * 32, hw0 = blockIdx.x * 32;
    int tx = threadIdx.x, ty = threadIdx.y;   // (32, 8)
    for (int t = ty; t < 32; t += 8) {
        int n = b * 1024 + hw0 + t;
        int gg = g_tok2g[n];
        tile[t][tx] = g_X[(size_t)gg * C + c0 + tx];
    }
    __syncthreads();
    int ibase = b * (C * 1024) + hw0;
    #pragma unroll
    for (int j = 0; j < 4; j++) {
        int c = c0 + ty + 8 * j;
        int idx = ibase + c * 1024 + tx;
        out32[idx] = tile[tx][ty + 8 * j] + s32[idx];
    }
}

// ---------------------------------------------------------------------------
// launch
// ---------------------------------------------------------------------------
extern "C" void kernel_launch(void* const* d_in, const int* in_sizes, int n_in,
                              void* d_out, int out_size) {
    const float* s4  = (const float*)d_in[0];
    const float* s8  = (const float*)d_in[1];
    const float* s16 = (const float*)d_in[2];
    const float* s32 = (const float*)d_in[3];
    const float* gw1 = (const float*)d_in[4];
    const float* gb1 = (const float*)d_in[5];
    const float* gw2 = (const float*)d_in[6];
    const float* gb2 = (const float*)d_in[7];
    const float* ew1 = (const float*)d_in[8];
    const float* eb1 = (const float*)d_in[9];
    const float* ew2 = (const float*)d_in[10];
    const float* eb2 = (const float*)d_in[11];
    float* out = (float*)d_out;

    transpose_k<<<dim3(32, 24, 8), dim3(32, 8)>>>(s32);

    // gate hidden: G1 = gelu(X @ gw1 + gb1)   (split-tf32) + s4 copy overlapped
    mma_gemm_k<0, 1><<<NB_COPY + MT * NT, 256>>>(
        gw1, gb1, (const float4*)s4, (float4*)out, S4_ELEMS / 4);

    // routing
    gate_k<<<(NTOK * 32) / 256, 256>>>(gw2, gb2);
    scan_k<<<1, 1>>>();
    perm_k<<<NTOK / 256, 256>>>();

    // expert up:   H = gelu(gather(X) @ ew1[e] + eb1[e])   (tf32) + s8 copy overlapped
    mma_gemm_k<1, 0><<<NB_COPY + MT * NT * NE, 256>>>(
        ew1, eb1, (const float4*)s8, (float4*)(out + OFF_S8), S8_ELEMS / 4);

    // expert down: Y = (H @ ew2[e] + eb2[e]) * gate_val    (tf32) + s16 copy overlapped
    mma_gemm_k<2, 0><<<NB_COPY + MT * NT * NE, 256>>>(
        ew2, eb2, (const float4*)s16, (float4*)(out + OFF_S16), S16_ELEMS / 4);

    // scatter + residual into out32
    scatter_k<<<dim3(32, 24, 8), dim3(32, 8)>>>(s32, out + OFF_S32);
}

// round 7
// speedup vs baseline: 1.8436x; 1.3342x over previous
#include <cuda_runtime.h>
#include <cuda_bf16.h>
#include <math.h>
#include <stdint.h>

// ---------------------------------------------------------------------------
// Problem constants
// ---------------------------------------------------------------------------
#define NTOK 8192           // 8 * 32 * 32 tokens at stride 32
#define C    768            // channels
#define K2C  384            // C/2 (k-pair rows of packed weights)
#define NE   4              // experts

#define S4_ELEMS  50331648  // 8*96*256*256
#define S8_ELEMS  25165824  // 8*192*128*128
#define S16_ELEMS 12582912  // 8*384*64*64
#define OFF_S8   50331648
#define OFF_S16  75497472
#define OFF_S32  88080384

// GEMM tiling (bf16 m16n8k16 mma path)
#define TBM 128
#define TBN 128
#define TBK 32              // k per smem stage (2 x k16 mma steps)
#define AS_W 20             // u32 words per A smem row (32 bf16 data + pad -> 40 bf16)
#define BS_W 136            // u32 words per B smem row (128 data + 8 pad)
#define A_STAGE_W (TBM * AS_W)        // 2560 words
#define B_STAGE_W ((TBK/2) * BS_W)    // 2176 words
#define SMEM_PLAIN_BYTES ((2*A_STAGE_W + 2*B_STAGE_W) * 4)          // 37888
#define SMEM_SPLIT_BYTES ((4*A_STAGE_W + 4*B_STAGE_W) * 4)          // 75776

#define MT (NTOK / TBM)     // 64 m-tiles
#define NT (C / TBN)        // 6  n-tiles
#define NB_COPY 148         // copy blocks PREPENDED per GEMM launch
#define NB_CONV 256         // expert-weight convert blocks (gate launch only)

// ---------------------------------------------------------------------------
// Scratch (device globals: no allocation allowed)
// ---------------------------------------------------------------------------
__device__ __nv_bfloat16 g_Xb[NTOK * C];   // tokens hi bf16
__device__ __nv_bfloat16 g_Xl[NTOK * C];   // tokens lo bf16 (split residual)
__device__ __nv_bfloat16 g_H [NTOK * C];   // expert hidden (compact, bf16)
__device__ float g_X [NTOK * C];           // Y (expert output, fp32, compact)
__device__ float g_G1[NTOK * C];           // gate hidden (fp32)
__device__ uint32_t g_gw1h[K2C * C];       // gate w1 hi, k-pair packed bf16x2
__device__ uint32_t g_gw1l[K2C * C];       // gate w1 lo
__device__ uint32_t g_ew1b[NE * K2C * C];  // expert w1 bf16 packed
__device__ uint32_t g_ew2b[NE * K2C * C];  // expert w2 bf16 packed
__device__ int   g_top[NTOK];
__device__ float g_gv[NTOK];
__device__ int   g_perm[NTOK];
__device__ int   g_tok2g[NTOK];
__device__ int   g_counts[NE];
__device__ int   g_offsets[NE + 1];
__device__ int   g_fill[NE];

// ---------------------------------------------------------------------------
// Helpers
// ---------------------------------------------------------------------------
__device__ __forceinline__ float gelu_tanh(float x) {
    float x3 = x * x * x;
    return 0.5f * x * (1.0f + tanhf(0.7978845608028654f * x + 0.035677408136300125f * x3));
}

__device__ __forceinline__ void cp_async16(uint32_t smem_dst, const void* gsrc, bool valid) {
    int sz = valid ? 16 : 0;
    asm volatile("cp.async.cg.shared.global [%0], [%1], 16, %2;\n"
                 :: "r"(smem_dst), "l"(gsrc), "r"(sz));
}
__device__ __forceinline__ void cp_commit() { asm volatile("cp.async.commit_group;\n"); }
__device__ __forceinline__ void cp_wait0()  { asm volatile("cp.async.wait_group 0;\n"); }

__device__ __forceinline__ void mma_bf16(float* c, const uint32_t* a, const uint32_t* b) {
    asm volatile(
        "mma.sync.aligned.m16n8k16.row.col.f32.bf16.bf16.f32 "
        "{%0,%1,%2,%3},{%4,%5,%6,%7},{%8,%9},{%0,%1,%2,%3};\n"
        : "+f"(c[0]), "+f"(c[1]), "+f"(c[2]), "+f"(c[3])
        : "r"(a[0]), "r"(a[1]), "r"(a[2]), "r"(a[3]), "r"(b[0]), "r"(b[1]));
}

// pack: word.lo = bf16(v0) (even k), word.hi = bf16(v1) (odd k)
__device__ __forceinline__ uint32_t pack_bf16x2(float v0, float v1) {
    uint32_t r;
    asm("cvt.rn.bf16x2.f32 %0, %1, %2;" : "=r"(r) : "f"(v1), "f"(v0));
    return r;
}

// grid-stride unrolled float4 copy (cnt4 must be a multiple of 1024)
__device__ __forceinline__ void do_copy(int blk, int tid,
                                        const float4* __restrict__ s,
                                        float4* __restrict__ d, int cnt4) {
    size_t i = (size_t)blk * 1024 + tid;
    const size_t stride = (size_t)NB_COPY * 1024;
    for (; i < (size_t)cnt4; i += stride) {
        float4 a = s[i];
        float4 b = s[i + 256];
        float4 c = s[i + 512];
        float4 e = s[i + 768];
        d[i]       = a;
        d[i + 256] = b;
        d[i + 512] = c;
        d[i + 768] = e;
    }
}

// ---------------------------------------------------------------------------
// 1. prep launch: BCHW->token transpose (hi/lo bf16) + gate-w1 split/pack
// ---------------------------------------------------------------------------
__global__ void prep_k(const float* __restrict__ s32, const float* __restrict__ gw1) {
    int blk = blockIdx.x;
    int tx = threadIdx.x, ty = threadIdx.y;   // (32, 8)

    if (blk < 6144) {
        __shared__ float tile[32][33];
        int bx = blk & 31;
        int t  = blk >> 5;
        int by = t % 24;
        int bz = t / 24;
        int c0 = by * 32, hw0 = bx * 32;
        if (blk == 0 && ty == 0 && tx < NE) g_counts[tx] = 0;
        const float* src = s32 + ((size_t)bz * C + c0) * 1024 + hw0;
        #pragma unroll
        for (int j = 0; j < 32; j += 8)
            tile[ty + j][tx] = src[(ty + j) * 1024 + tx];
        __syncthreads();
        size_t dbase = ((size_t)(bz * 1024 + hw0)) * C + c0;
        #pragma unroll
        for (int j = 0; j < 32; j += 8) {
            float x = tile[tx][ty + j];
            __nv_bfloat16 h = __float2bfloat16(x);
            float r = x - __bfloat162float(h);
            size_t idx = dbase + (size_t)(ty + j) * C + tx;
            g_Xb[idx] = h;
            g_Xl[idx] = __float2bfloat16(r);
        }
    } else {
        // gate w1 split: [K2C][C] words
        int tid = ty * 32 + tx;
        const int total = K2C * C;
        for (int w = (blk - 6144) * 256 + tid; w < total; w += 256 * 256) {
            int k2 = w / C, n = w - k2 * C;
            float w0 = gw1[(size_t)(2 * k2) * C + n];
            float w1 = gw1[(size_t)(2 * k2 + 1) * C + n];
            float h0 = __bfloat162float(__float2bfloat16(w0));
            float h1 = __bfloat162float(__float2bfloat16(w1));
            g_gw1h[w] = pack_bf16x2(h0, h1);
            g_gw1l[w] = pack_bf16x2(w0 - h0, w1 - h1);
        }
    }
}

// ---------------------------------------------------------------------------
// bf16 tensor-core GEMM, double-buffered cp.async, BK=32, copy blocks first.
//   MODE 0 (split-bf16): G1 = gelu(X @ gw1 + b1)           A=Xb/Xl, Out=g_G1
//   MODE 1 (plain bf16): H  = gelu(gather(Xb) @ ew1 + b1)  Out=g_H (bf16)
//   MODE 2 (plain bf16): Y  = (H @ ew2 + b2) * gate_val    Out=g_X (fp32)
// MODE 0 additionally hosts the expert-weight convert blocks.
// ---------------------------------------------------------------------------
template <int MODE>
__launch_bounds__(256)
__global__ void mma_gemm_k(const float* __restrict__ Ball,
                           const float4* __restrict__ csrc, float4* __restrict__ cdst, int cnt4,
                           const float* __restrict__ cvt1, const float* __restrict__ cvt2,
                           int nbPre) {
    constexpr bool SPLIT = (MODE == 0);
    const int blk = blockIdx.x;
    const int tid = threadIdx.x;

    // ---- copy role -------------------------------------------------------
    if (blk < NB_COPY) { do_copy(blk, tid, csrc, cdst, cnt4); return; }

    // ---- expert weight convert role (gate launch only) -------------------
    if (MODE == 0 && blk < nbPre) {
        const int cb = blk - NB_COPY;
        const int WCNT = NE * K2C * C;
        for (int w = cb * 256 + tid; w < 2 * WCNT; w += NB_CONV * 256) {
            int wi = w;
            const float* src; uint32_t* dst;
            if (wi < WCNT) { src = cvt1; dst = g_ew1b; }
            else           { wi -= WCNT; src = cvt2; dst = g_ew2b; }
            int k2g = wi / C, n = wi - k2g * C;
            float w0 = src[(size_t)(2 * k2g) * C + n];
            float w1 = src[(size_t)(2 * k2g + 1) * C + n];
            dst[wi] = pack_bf16x2(w0, w1);
        }
        return;
    }

    // ---- GEMM role -------------------------------------------------------
    const int gblk = blk - nbPre;
    int e, bx, by;
    if (MODE == 0) { e = 0; bx = gblk & (MT - 1); by = gblk >> 6; }
    else { e = gblk / (MT * NT); int r = gblk - e * (MT * NT); bx = r & (MT - 1); by = r >> 6; }

    int base, cnt;
    if (MODE == 0) { base = 0; cnt = NTOK; }
    else           { base = g_offsets[e]; cnt = g_offsets[e + 1] - base; }

    const int m0 = bx * TBM;
    if (m0 >= cnt) return;
    const int n0 = by * TBN;

    const uint32_t* Wh = (MODE == 0) ? g_gw1h
                        : (MODE == 1) ? (g_ew1b + (size_t)e * K2C * C)
                                      : (g_ew2b + (size_t)e * K2C * C);
    const uint32_t* Wl = g_gw1l;   // used only when SPLIT
    const float* bias  = Ball + ((MODE == 0) ? 0 : e * C);

    extern __shared__ uint32_t sm[];
    uint32_t* AhB = sm;
    uint32_t* AlB = sm + 2 * A_STAGE_W;
    uint32_t* BhB = sm + (SPLIT ? 4 : 2) * A_STAGE_W;
    uint32_t* BlB = BhB + 2 * B_STAGE_W;
    const uint32_t sAh = (uint32_t)__cvta_generic_to_shared(AhB);
    const uint32_t sAl = (uint32_t)__cvta_generic_to_shared(AlB);
    const uint32_t sBh = (uint32_t)__cvta_generic_to_shared(BhB);
    const uint32_t sBl = (uint32_t)__cvta_generic_to_shared(BlB);

    const int wid  = tid >> 5;
    const int lane = tid & 31;
    const int g    = lane >> 2;
    const int tig  = lane & 3;
    const int mW   = (wid & 1) * 64;
    const int nW   = (wid >> 1) * 32;

    // A loader: 2 x 16B chunks/thread/stage (per array). 128 rows x 64B.
    const __nv_bfloat16* Asrc = (MODE == 2) ? g_H : g_Xb;
    const uint8_t* srcA[2]; const uint8_t* srcAL[2]; uint32_t dstA[2]; bool vA[2];
    #pragma unroll
    for (int i = 0; i < 2; i++) {
        int q = tid + i * 256;
        int chunk = q >> 7;          // 0..3
        int row   = q & 127;
        int m = m0 + row;
        bool v = (m < cnt);
        int ar = 0;
        if (v) {
            if      (MODE == 1) ar = g_perm[base + m];
            else if (MODE == 2) ar = base + m;
            else                ar = m;
        }
        size_t boff = (size_t)ar * C * 2 + chunk * 16;
        srcA[i]  = (const uint8_t*)Asrc + boff;
        srcAL[i] = (const uint8_t*)g_Xl + boff;
        dstA[i]  = (uint32_t)(row * AS_W + chunk * 4) * 4u;
        vA[i] = v;
    }
    // B loader: 2 x 16B chunks/thread/stage. 16 k2-rows x 512B.
    size_t srcBoff[2]; uint32_t dstB[2];
    #pragma unroll
    for (int i = 0; i < 2; i++) {
        int q = tid + i * 256;
        int k2r = q >> 5;            // 0..15
        int c   = q & 31;            // 0..31
        srcBoff[i] = (size_t)k2r * C + n0 + c * 4;
        dstB[i]    = (uint32_t)(k2r * BS_W + c * 4) * 4u;
    }

    float acc[4][4][4];
    #pragma unroll
    for (int mt = 0; mt < 4; mt++)
        #pragma unroll
        for (int nt = 0; nt < 4; nt++)
            #pragma unroll
            for (int r = 0; r < 4; r++) acc[mt][nt][r] = 0.f;

    const int T = C / TBK;  // 24

    // prologue: stage 0
    #pragma unroll
    for (int i = 0; i < 2; i++) cp_async16(sAh + dstA[i], srcA[i], vA[i]);
    if (SPLIT)
        #pragma unroll
        for (int i = 0; i < 2; i++) cp_async16(sAl + dstA[i], srcAL[i], vA[i]);
    #pragma unroll
    for (int i = 0; i < 2; i++) cp_async16(sBh + dstB[i], Wh + srcBoff[i], true);
    if (SPLIT)
        #pragma unroll
        for (int i = 0; i < 2; i++) cp_async16(sBl + dstB[i], Wl + srcBoff[i], true);
    cp_commit();

    for (int t = 0; t < T; t++) {
        const int cur = t & 1;
        cp_wait0();
        __syncthreads();

        if (t + 1 < T) {
            const int nxt = cur ^ 1;
            const int kb = (t + 1) * (TBK * 2);       // bytes into A rows
            const size_t kw = (size_t)(t + 1) * (TBK / 2) * C;  // words into W
            #pragma unroll
            for (int i = 0; i < 2; i++)
                cp_async16(sAh + nxt * (A_STAGE_W * 4) + dstA[i], srcA[i] + kb, vA[i]);
            if (SPLIT)
                #pragma unroll
                for (int i = 0; i < 2; i++)
                    cp_async16(sAl + nxt * (A_STAGE_W * 4) + dstA[i], srcAL[i] + kb, vA[i]);
            #pragma unroll
            for (int i = 0; i < 2; i++)
                cp_async16(sBh + nxt * (B_STAGE_W * 4) + dstB[i], Wh + srcBoff[i] + kw, true);
            if (SPLIT)
                #pragma unroll
                for (int i = 0; i < 2; i++)
                    cp_async16(sBl + nxt * (B_STAGE_W * 4) + dstB[i], Wl + srcBoff[i] + kw, true);
            cp_commit();
        }

        const uint32_t* Ahc = AhB + cur * A_STAGE_W;
        const uint32_t* Alc = AlB + cur * A_STAGE_W;
        const uint32_t* Bhc = BhB + cur * B_STAGE_W;
        const uint32_t* Blc = BlB + cur * B_STAGE_W;

        #pragma unroll
        for (int ks = 0; ks < 2; ks++) {
            const int k8 = ks * 8;
            uint32_t bh[4][2], bl[4][2];
            #pragma unroll
            for (int nt = 0; nt < 4; nt++) {
                const int n = nW + nt * 8 + g;
                bh[nt][0] = Bhc[(k8 + tig)     * BS_W + n];
                bh[nt][1] = Bhc[(k8 + tig + 4) * BS_W + n];
                if (SPLIT) {
                    bl[nt][0] = Blc[(k8 + tig)     * BS_W + n];
                    bl[nt][1] = Blc[(k8 + tig + 4) * BS_W + n];
                }
            }
            #pragma unroll
            for (int mt = 0; mt < 4; mt++) {
                const int r0 = mW + mt * 16 + g;
                uint32_t ah[4], al[4];
                ah[0] = Ahc[ r0      * AS_W + k8 + tig];
                ah[1] = Ahc[(r0 + 8) * AS_W + k8 + tig];
                ah[2] = Ahc[ r0      * AS_W + k8 + tig + 4];
                ah[3] = Ahc[(r0 + 8) * AS_W + k8 + tig + 4];
                if (SPLIT) {
                    al[0] = Alc[ r0      * AS_W + k8 + tig];
                    al[1] = Alc[(r0 + 8) * AS_W + k8 + tig];
                    al[2] = Alc[ r0      * AS_W + k8 + tig + 4];
                    al[3] = Alc[(r0 + 8) * AS_W + k8 + tig + 4];
                }
                #pragma unroll
                for (int nt = 0; nt < 4; nt++) {
                    mma_bf16(acc[mt][nt], ah, bh[nt]);
                    if (SPLIT) {
                        mma_bf16(acc[mt][nt], al, bh[nt]);
                        mma_bf16(acc[mt][nt], ah, bl[nt]);
                    }
                }
            }
        }
        __syncthreads();
    }

    // ---- epilogue
    #pragma unroll
    for (int mt = 0; mt < 4; mt++) {
        #pragma unroll
        for (int half = 0; half < 2; half++) {
            const int m = m0 + mW + mt * 16 + g + half * 8;
            if (m >= cnt) continue;
            float gv = 1.f;
            if (MODE == 2) gv = g_gv[g_perm[base + m]];
            #pragma unroll
            for (int nt = 0; nt < 4; nt++) {
                const int col = n0 + nW + nt * 8 + tig * 2;
                float2 bv = *(const float2*)(bias + col);
                float v0 = acc[mt][nt][half * 2 + 0] + bv.x;
                float v1 = acc[mt][nt][half * 2 + 1] + bv.y;
                if (MODE == 0) {
                    float* orow = g_G1 + (size_t)m * C;
                    *(float2*)(orow + col) = make_float2(gelu_tanh(v0), gelu_tanh(v1));
                } else if (MODE == 1) {
                    __nv_bfloat162* hrow = (__nv_bfloat162*)(g_H + (size_t)(base + m) * C);
                    hrow[col >> 1] = __floats2bfloat162_rn(gelu_tanh(v0), gelu_tanh(v1));
                } else {
                    float* orow = g_X + (size_t)(base + m) * C;
                    *(float2*)(orow + col) = make_float2(v0 * gv, v1 * gv);
                }
            }
        }
    }
}

// ---------------------------------------------------------------------------
// 3. logits = G1 @ gate_w2 + b2 -> softmax -> top-1 idx + gate value
// ---------------------------------------------------------------------------
__global__ void gate_k(const float* __restrict__ w2, const float* __restrict__ b2) {
    int warp = (blockIdx.x * blockDim.x + threadIdx.x) >> 5;
    int lane = threadIdx.x & 31;
    if (warp >= NTOK) return;
    const float* g = g_G1 + (size_t)warp * C;
    float l0 = 0.f, l1 = 0.f, l2 = 0.f, l3 = 0.f;
    for (int c = lane; c < C; c += 32) {
        float x = g[c];
        float4 wv = *(const float4*)(w2 + c * 4);
        l0 = fmaf(x, wv.x, l0);
        l1 = fmaf(x, wv.y, l1);
        l2 = fmaf(x, wv.z, l2);
        l3 = fmaf(x, wv.w, l3);
    }
    #pragma unroll
    for (int o = 16; o; o >>= 1) {
        l0 += __shfl_xor_sync(0xffffffffu, l0, o);
        l1 += __shfl_xor_sync(0xffffffffu, l1, o);
        l2 += __shfl_xor_sync(0xffffffffu, l2, o);
        l3 += __shfl_xor_sync(0xffffffffu, l3, o);
    }
    if (lane == 0) {
        l0 += b2[0]; l1 += b2[1]; l2 += b2[2]; l3 += b2[3];
        float m = l0; int idx = 0;
        if (l1 > m) { m = l1; idx = 1; }   // strict '>' keeps first max (jnp.argmax)
        if (l2 > m) { m = l2; idx = 2; }
        if (l3 > m) { m = l3; idx = 3; }
        float s = expf(l0 - m) + expf(l1 - m) + expf(l2 - m) + expf(l3 - m);
        g_top[warp] = idx;
        g_gv[warp]  = 1.0f / s;            // exp(l_top - m) == 1
        atomicAdd(&g_counts[idx], 1);
    }
}

// ---------------------------------------------------------------------------
// 4. tiny exclusive scan + reset fill cursors
// ---------------------------------------------------------------------------
__global__ void scan_k() {
    if (threadIdx.x == 0) {
        int s = 0;
        #pragma unroll
        for (int e = 0; e < NE; e++) {
            g_offsets[e] = s;
            s += g_counts[e];
            g_fill[e] = 0;
        }
        g_offsets[NE] = s;
    }
}

// ---------------------------------------------------------------------------
// 5. build permutation (token -> compact position, grouped by expert)
// ---------------------------------------------------------------------------
__global__ void perm_k() {
    int n = blockIdx.x * blockDim.x + threadIdx.x;
    if (n >= NTOK) return;
    int e = g_top[n];
    int pos = atomicAdd(&g_fill[e], 1);
    int gg = g_offsets[e] + pos;
    g_perm[gg]  = n;
    g_tok2g[n]  = gg;
}

// ---------------------------------------------------------------------------
// 8. coalesced scatter back to BCHW + residual
// ---------------------------------------------------------------------------
__global__ void scatter_k(const float* __restrict__ s32, float* __restrict__ out32) {
    __shared__ float tile[32][33];
    int b = blockIdx.z, c0 = blockIdx.y * 32, hw0 = blockIdx.x * 32;
    int tx = threadIdx.x, ty = threadIdx.y;   // (32, 8)
    for (int t = ty; t < 32; t += 8) {
        int n = b * 1024 + hw0 + t;
        int gg = g_tok2g[n];
        tile[t][tx] = g_X[(size_t)gg * C + c0 + tx];
    }
    __syncthreads();
    int ibase = b * (C * 1024) + hw0;
    #pragma unroll
    for (int j = 0; j < 4; j++) {
        int c = c0 + ty + 8 * j;
        int idx = ibase + c * 1024 + tx;
        out32[idx] = tile[tx][ty + 8 * j] + s32[idx];
    }
}

// ---------------------------------------------------------------------------
// launch
// ---------------------------------------------------------------------------
extern "C" void kernel_launch(void* const* d_in, const int* in_sizes, int n_in,
                              void* d_out, int out_size) {
    const float* s4  = (const float*)d_in[0];
    const float* s8  = (const float*)d_in[1];
    const float* s16 = (const float*)d_in[2];
    const float* s32 = (const float*)d_in[3];
    const float* gw1 = (const float*)d_in[4];
    const float* gb1 = (const float*)d_in[5];
    const float* gw2 = (const float*)d_in[6];
    const float* gb2 = (const float*)d_in[7];
    const float* ew1 = (const float*)d_in[8];
    const float* eb1 = (const float*)d_in[9];
    const float* ew2 = (const float*)d_in[10];
    const float* eb2 = (const float*)d_in[11];
    float* out = (float*)d_out;

    // split-gate kernel needs > 48KB dynamic smem
    cudaFuncSetAttribute(mma_gemm_k<0>, cudaFuncAttributeMaxDynamicSharedMemorySize, SMEM_SPLIT_BYTES);

    // prep: transpose s32 -> hi/lo bf16 tokens, split/pack gate w1
    prep_k<<<6144 + 256, dim3(32, 8)>>>(s32, gw1);

    // gate hidden (split-bf16) + s4 copy + expert-weight convert, one launch
    mma_gemm_k<0><<<NB_COPY + NB_CONV + MT * NT, 256, SMEM_SPLIT_BYTES>>>(
        gb1, (const float4*)s4, (float4*)out, S4_ELEMS / 4, ew1, ew2, NB_COPY + NB_CONV);

    // routing
    gate_k<<<(NTOK * 32) / 256, 256>>>(gw2, gb2);
    scan_k<<<1, 1>>>();
    perm_k<<<NTOK / 256, 256>>>();

    // expert up (bf16) + s8 copy
    mma_gemm_k<1><<<NB_COPY + MT * NT * NE, 256, SMEM_PLAIN_BYTES>>>(
        eb1, (const float4*)s8, (float4*)(out + OFF_S8), S8_ELEMS / 4,
        nullptr, nullptr, NB_COPY);

    // expert down (bf16) + s16 copy
    mma_gemm_k<2><<<NB_COPY + MT * NT * NE, 256, SMEM_PLAIN_BYTES>>>(
        eb2, (const float4*)s16, (float4*)(out + OFF_S16), S16_ELEMS / 4,
        nullptr, nullptr, NB_COPY);

    // scatter + residual into out32
    scatter_k<<<dim3(32, 24, 8), dim3(32, 8)>>>(s32, out + OFF_S32);
}